// round 10
// baseline (speedup 1.0000x reference)
#include <cuda_runtime.h>
#include <cuda_fp16.h>
#include <cstdint>
#include <math.h>

// Problem constants
#define NT   2048
#define NH   2048
#define NI   5632
#define NEXP 4
#define NTOPK 2

#define BK      32
#define HSTRIDE 40               // halves per smem row (80B pitch), conflict-free
#define NSTAGE  4
#define THREADS 256
#define ASTG (256 * HSTRIDE * 2)   // 20480 per A tile-stage
#define BSTG (128 * HSTRIDE * 2)   // 10240 per B tile-stage

// ---------------- device scratch ----------------
__device__ int    g_cnt[NEXP];
__device__ int    g_tok[NEXP * NT];
__device__ float  g_wgt[NEXP * NT];
__device__ __half g_act[(size_t)NEXP * NT * NI];
__device__ __half g_w13h[(size_t)NEXP * 2 * NI * NH];  // fp16 W13 (active experts)
__device__ __half g_w2h[(size_t)NEXP * NH * NI];       // fp16 W2
__device__ __half g_hidh[(size_t)NT * NH];             // fp16 hidden

// ---------------- shared layout ----------------
struct SMem {
  __half A[NSTAGE][256 * HSTRIDE];   // 4 x 20KB
  __half B[NSTAGE][128 * HSTRIDE];   // 4 x 10KB
  int    toks[256];
  float  wgts[256];
};
#define SMEM_BYTES ((int)sizeof(SMem))

// ---------------- helpers ----------------
__device__ __forceinline__ uint32_t smem_u32(const void* p) {
  uint32_t a;
  asm("{ .reg .u64 t; cvta.to.shared.u64 t, %1; cvt.u32.u64 %0, t; }" : "=r"(a) : "l"(p));
  return a;
}
__device__ __forceinline__ void cpasync16(uint32_t dst, const void* src) {
  asm volatile("cp.async.cg.shared.global [%0], [%1], 16;" :: "r"(dst), "l"(src));
}
#define CP_COMMIT() asm volatile("cp.async.commit_group;" ::: "memory")
#define CP_WAIT2()  asm volatile("cp.async.wait_group 2;" ::: "memory")
__device__ __forceinline__ void mma16(float* c, const uint32_t* a, const uint32_t* b) {
  asm volatile(
      "mma.sync.aligned.m16n8k16.row.col.f32.f16.f16.f32 "
      "{%0,%1,%2,%3}, {%4,%5,%6,%7}, {%8,%9}, {%0,%1,%2,%3};"
      : "+f"(c[0]), "+f"(c[1]), "+f"(c[2]), "+f"(c[3])
      : "r"(a[0]), "r"(a[1]), "r"(a[2]), "r"(a[3]), "r"(b[0]), "r"(b[1]));
}
__device__ __forceinline__ void ldsm4(uint32_t r[4], uint32_t addr) {
  asm volatile("ldmatrix.sync.aligned.m8n8.x4.shared.b16 {%0,%1,%2,%3}, [%4];"
               : "=r"(r[0]), "=r"(r[1]), "=r"(r[2]), "=r"(r[3]) : "r"(addr));
}

// ---------------- routing ----------------
__global__ void zero_cnt_kernel() {
  if (threadIdx.x < NEXP) g_cnt[threadIdx.x] = 0;
}
__global__ void route_kernel(const int* __restrict__ ids, const float* __restrict__ tw) {
  int t = blockIdx.x * blockDim.x + threadIdx.x;
  if (t >= NT) return;
  int e0 = ids[t * NTOPK + 0] & 3;
  int e1 = ids[t * NTOPK + 1] & 3;
  float w0 = tw[t * NTOPK + 0], w1 = tw[t * NTOPK + 1];
  if (e0 == e1) {
    int p = atomicAdd(&g_cnt[e0], 1);
    g_tok[e0 * NT + p] = t; g_wgt[e0 * NT + p] = w0 + w1;
  } else {
    int p0 = atomicAdd(&g_cnt[e0], 1);
    g_tok[e0 * NT + p0] = t; g_wgt[e0 * NT + p0] = w0;
    int p1 = atomicAdd(&g_cnt[e1], 1);
    g_tok[e1 * NT + p1] = t; g_wgt[e1 * NT + p1] = w1;
  }
}

// ---------------- f32 -> fp16 conversion (once per launch) -----------------
__global__ void cvt_f2h(const float4* __restrict__ src, int which, int n4) {
  int i = blockIdx.x * blockDim.x + threadIdx.x;
  if (i >= n4) return;
  __half* dst = (which == 0) ? g_w13h : (which == 1) ? g_w2h : g_hidh;
  float4 v = src[i];
  __half2 h0 = __floats2half2_rn(v.x, v.y);
  __half2 h1 = __floats2half2_rn(v.z, v.w);
  uint2 u = make_uint2(*(uint32_t*)&h0, *(uint32_t*)&h1);
  *(uint2*)(dst + (size_t)i * 4) = u;
}

// ---------------- fragment compute: warp tile 64(m) x 64(n) -----------------
__device__ __forceinline__ void compute_tile(uint32_t aB, uint32_t bB,
                                             float acc[4][8][4]) {
#pragma unroll
  for (int s = 0; s < 2; ++s) {            // two k16 steps per BK=32
    uint32_t a[4][4], b[4][4];
#pragma unroll
    for (int mt = 0; mt < 4; ++mt) ldsm4(a[mt], aB + mt * 1280 + s * 32);
#pragma unroll
    for (int p = 0; p < 4; ++p)  ldsm4(b[p], bB + p * 1280 + s * 32);
#pragma unroll
    for (int mt = 0; mt < 4; ++mt)
#pragma unroll
      for (int p = 0; p < 4; ++p) {
        mma16(acc[mt][2 * p],     a[mt], &b[p][0]);
        mma16(acc[mt][2 * p + 1], a[mt], &b[p][2]);
      }
  }
}

// ---------------- GEMM1 + fused SiLU*gate -----------------------------------
// tile 256(m) x 128(B-rows: interleaved W1/W3 of 64 I-cols), K=NH
__global__ __launch_bounds__(THREADS, 1) void gemm1_tc() {
  const int e   = blockIdx.z;
  const int cnt = g_cnt[e];
  const int m0  = blockIdx.x * 256;
  if (m0 >= cnt) return;
  const int n0 = blockIdx.y * 64;    // I columns

  extern __shared__ char smraw[];
  SMem& sm = *(SMem*)smraw;
  const int tid = threadIdx.x;

  {
    int m = m0 + tid;
    sm.toks[tid] = g_tok[e * NT + (m < cnt ? m : cnt - 1)];
  }
  __syncthreads();

  // loaders: A one row/thread (4x16B); B one row per 2 threads (2x16B each)
  const __half* asrc = g_hidh + (size_t)sm.toks[tid] * NH;
  const int rB = tid >> 1, segB = tid & 1;          // segB: half-row selector
  const __half* bsrc = g_w13h +
      ((size_t)e * 2 * NI + (size_t)(rB & 1) * NI + n0 + (rB >> 1)) * NH + segB * 16;

  const uint32_t smA = smem_u32(&sm.A[0][0]);
  const uint32_t smB = smem_u32(&sm.B[0][0]);
  const uint32_t dA = smA + tid * 80;
  const uint32_t dB = smB + rB * 80 + segB * 32;    // bytes

#pragma unroll
  for (int s = 0; s < NSTAGE - 1; ++s) {
#pragma unroll
    for (int g = 0; g < 4; ++g)
      cpasync16(dA + s * ASTG + g * 16, asrc + s * BK + g * 8);
    cpasync16(dB + s * BSTG,      bsrc + s * BK);
    cpasync16(dB + s * BSTG + 16, bsrc + s * BK + 8);
    CP_COMMIT();
  }

  const int lane = tid & 31, warp = tid >> 5;
  const int wM = warp & 3, wN = warp >> 2;
  const int gid = lane >> 2, tg = lane & 3;
  const uint32_t aBase = smA +
      (uint32_t)(((wM * 64 + (lane & 7) + ((lane >> 3) & 1) * 8) * HSTRIDE +
                  (lane >> 4) * 8) * 2);
  const uint32_t bBase = smB +
      (uint32_t)(((wN * 64 + (lane & 7) + (lane >> 4) * 8) * HSTRIDE +
                  ((lane >> 3) & 1) * 8) * 2);

  float acc[4][8][4];
#pragma unroll
  for (int mt = 0; mt < 4; ++mt)
#pragma unroll
    for (int nt = 0; nt < 8; ++nt)
#pragma unroll
      for (int q = 0; q < 4; ++q) acc[mt][nt][q] = 0.0f;

  const int KB = NH / BK;   // 64
  for (int kb = 0; kb < KB; ++kb) {
    CP_WAIT2();
    __syncthreads();
    const int st = kb & (NSTAGE - 1);
    compute_tile(aBase + st * ASTG, bBase + st * BSTG, acc);
    const int kn = kb + NSTAGE - 1;
    if (kn < KB) {
      const int sn = kn & (NSTAGE - 1);
#pragma unroll
      for (int g = 0; g < 4; ++g)
        cpasync16(dA + sn * ASTG + g * 16, asrc + kn * BK + g * 8);
      cpasync16(dB + sn * BSTG,      bsrc + kn * BK);
      cpasync16(dB + sn * BSTG + 16, bsrc + kn * BK + 8);
    }
    CP_COMMIT();
  }

  // epilogue: act = silu(g1)*g3 (c0=g1, c1=g3 via interleaved B rows)
#pragma unroll
  for (int mt = 0; mt < 4; ++mt) {
    const int mrow0 = m0 + wM * 64 + mt * 16 + gid;
    const int mrow1 = mrow0 + 8;
#pragma unroll
    for (int p = 0; p < 4; ++p)
#pragma unroll
      for (int b8 = 0; b8 < 2; ++b8) {
        const int nt = 2 * p + b8;
        const int i = n0 + wN * 32 + p * 8 + b8 * 4 + tg;
        float g1 = acc[mt][nt][0], g3 = acc[mt][nt][1];
        float v0 = g1 / (1.0f + __expf(-g1)) * g3;
        g1 = acc[mt][nt][2]; g3 = acc[mt][nt][3];
        float v1 = g1 / (1.0f + __expf(-g1)) * g3;
        if (mrow0 < cnt) g_act[((size_t)e * NT + mrow0) * NI + i] = __float2half_rn(v0);
        if (mrow1 < cnt) g_act[((size_t)e * NT + mrow1) * NI + i] = __float2half_rn(v1);
      }
  }
}

// ---------------- GEMM2 + weighted scatter -----------------------------------
// tile 256(m) x 128(h), K=NI
__global__ __launch_bounds__(THREADS, 1) void gemm2_tc(float* __restrict__ out) {
  const int e   = blockIdx.z;
  const int cnt = g_cnt[e];
  const int m0  = blockIdx.x * 256;
  if (m0 >= cnt) return;
  const int n0 = blockIdx.y * 128;

  extern __shared__ char smraw[];
  SMem& sm = *(SMem*)smraw;
  const int tid = threadIdx.x;

  {
    int m = m0 + tid;
    int mc = m < cnt ? m : cnt - 1;
    sm.toks[tid] = g_tok[e * NT + mc];
    sm.wgts[tid] = g_wgt[e * NT + mc];
  }
  __syncthreads();

  const int mA = (m0 + tid) < cnt ? (m0 + tid) : cnt - 1;
  const __half* asrc = g_act + ((size_t)e * NT + mA) * NI;
  const int rB = tid >> 1, segB = tid & 1;
  const __half* bsrc = g_w2h + ((size_t)e * NH + n0 + rB) * NI + segB * 16;

  const uint32_t smA = smem_u32(&sm.A[0][0]);
  const uint32_t smB = smem_u32(&sm.B[0][0]);
  const uint32_t dA = smA + tid * 80;
  const uint32_t dB = smB + rB * 80 + segB * 32;

#pragma unroll
  for (int s = 0; s < NSTAGE - 1; ++s) {
#pragma unroll
    for (int g = 0; g < 4; ++g)
      cpasync16(dA + s * ASTG + g * 16, asrc + s * BK + g * 8);
    cpasync16(dB + s * BSTG,      bsrc + s * BK);
    cpasync16(dB + s * BSTG + 16, bsrc + s * BK + 8);
    CP_COMMIT();
  }

  const int lane = tid & 31, warp = tid >> 5;
  const int wM = warp & 3, wN = warp >> 2;
  const int gid = lane >> 2, tg = lane & 3;
  const uint32_t aBase = smA +
      (uint32_t)(((wM * 64 + (lane & 7) + ((lane >> 3) & 1) * 8) * HSTRIDE +
                  (lane >> 4) * 8) * 2);
  const uint32_t bBase = smB +
      (uint32_t)(((wN * 64 + (lane & 7) + (lane >> 4) * 8) * HSTRIDE +
                  ((lane >> 3) & 1) * 8) * 2);

  float acc[4][8][4];
#pragma unroll
  for (int mt = 0; mt < 4; ++mt)
#pragma unroll
    for (int nt = 0; nt < 8; ++nt)
#pragma unroll
      for (int q = 0; q < 4; ++q) acc[mt][nt][q] = 0.0f;

  const int KB = NI / BK;   // 176
  for (int kb = 0; kb < KB; ++kb) {
    CP_WAIT2();
    __syncthreads();
    const int st = kb & (NSTAGE - 1);
    compute_tile(aBase + st * ASTG, bBase + st * BSTG, acc);
    const int kn = kb + NSTAGE - 1;
    if (kn < KB) {
      const int sn = kn & (NSTAGE - 1);
#pragma unroll
      for (int g = 0; g < 4; ++g)
        cpasync16(dA + sn * ASTG + g * 16, asrc + kn * BK + g * 8);
      cpasync16(dB + sn * BSTG,      bsrc + kn * BK);
      cpasync16(dB + sn * BSTG + 16, bsrc + kn * BK + 8);
    }
    CP_COMMIT();
  }

  // epilogue: out[tok, h] += wgt * acc
#pragma unroll
  for (int mt = 0; mt < 4; ++mt) {
    const int lr0 = wM * 64 + mt * 16 + gid;
    const int lr1 = lr0 + 8;
    const bool v0 = (m0 + lr0) < cnt;
    const bool v1 = (m0 + lr1) < cnt;
    const int   t0 = sm.toks[lr0], t1 = sm.toks[lr1];
    const float w0 = sm.wgts[lr0], w1 = sm.wgts[lr1];
#pragma unroll
    for (int p = 0; p < 4; ++p)
#pragma unroll
      for (int b8 = 0; b8 < 2; ++b8) {
        const int nt = 2 * p + b8;
        const int h = n0 + wN * 64 + p * 16 + b8 * 8 + 2 * tg;
        if (v0) {
          atomicAdd(&out[(size_t)t0 * NH + h],     w0 * acc[mt][nt][0]);
          atomicAdd(&out[(size_t)t0 * NH + h + 1], w0 * acc[mt][nt][1]);
        }
        if (v1) {
          atomicAdd(&out[(size_t)t1 * NH + h],     w1 * acc[mt][nt][2]);
          atomicAdd(&out[(size_t)t1 * NH + h + 1], w1 * acc[mt][nt][3]);
        }
      }
  }
}

// ---------------- launcher ----------------
extern "C" void kernel_launch(void* const* d_in, const int* in_sizes, int n_in,
                              void* d_out, int out_size) {
  const float* hidden = (const float*)d_in[0];
  const float* w13    = (const float*)d_in[1];
  const float* w2     = (const float*)d_in[2];
  const float* tw     = (const float*)d_in[3];
  const int*   ids    = (const int*)d_in[4];
  float*       out    = (float*)d_out;
  (void)in_sizes; (void)n_in;

  cudaFuncSetAttribute(gemm1_tc, cudaFuncAttributeMaxDynamicSharedMemorySize, SMEM_BYTES);
  cudaFuncSetAttribute(gemm2_tc, cudaFuncAttributeMaxDynamicSharedMemorySize, SMEM_BYTES);

  cudaMemsetAsync(out, 0, (size_t)out_size * sizeof(float), 0);
  zero_cnt_kernel<<<1, 32>>>();
  route_kernel<<<(NT + 255) / 256, 256>>>(ids, tw);

  // f32 -> fp16 conversions (active experts only: first 4 of 8)
  const int n4_w13 = NEXP * 2 * NI * NH / 4;
  const int n4_w2  = NEXP * NH * NI / 4;
  const int n4_hid = NT * NH / 4;
  cvt_f2h<<<(n4_w13 + 255) / 256, 256>>>((const float4*)w13, 0, n4_w13);
  cvt_f2h<<<(n4_w2  + 255) / 256, 256>>>((const float4*)w2,  1, n4_w2);
  cvt_f2h<<<(n4_hid + 255) / 256, 256>>>((const float4*)hidden, 2, n4_hid);

  gemm1_tc<<<dim3(NT / 256, NI / 64, NEXP), THREADS, SMEM_BYTES>>>();
  gemm2_tc<<<dim3(NT / 256, NH / 128, NEXP), THREADS, SMEM_BYTES>>>(out);
}

// round 12
// speedup vs baseline: 1.0941x; 1.0941x over previous
#include <cuda_runtime.h>
#include <cuda_fp16.h>
#include <cstdint>
#include <math.h>

// Problem constants
#define NT   2048
#define NH   2048
#define NI   5632
#define NEXP 4
#define NTOPK 2

#define BK      64
#define HSTRIDE 72               // halves per smem row (144B pitch): LDSM conflict-free
#define NSTAGE  3
#define THREADS 256
#define ASTG (128 * HSTRIDE * 2)   // 18432 per A tile-stage
#define BSTG (128 * HSTRIDE * 2)   // 18432 per B tile-stage

// ---------------- device scratch ----------------
__device__ int    g_cnt[NEXP];
__device__ int    g_tok[NEXP * NT];
__device__ float  g_wgt[NEXP * NT];
__device__ __half g_act[(size_t)NEXP * NT * NI];
__device__ __half g_w13h[(size_t)NEXP * 2 * NI * NH];  // fp16 W13 (active experts)
__device__ __half g_w2h[(size_t)NEXP * NH * NI];       // fp16 W2
__device__ __half g_hidh[(size_t)NT * NH];             // fp16 hidden

// ---------------- shared layout ----------------
struct SMem {
  __half A[NSTAGE][128 * HSTRIDE];   // 3 x 18KB
  __half B[NSTAGE][128 * HSTRIDE];   // 3 x 18KB
  int    toks[128];
  float  wgts[128];
};
#define SMEM_BYTES ((int)sizeof(SMem))

// ---------------- helpers ----------------
__device__ __forceinline__ uint32_t smem_u32(const void* p) {
  uint32_t a;
  asm("{ .reg .u64 t; cvta.to.shared.u64 t, %1; cvt.u32.u64 %0, t; }" : "=r"(a) : "l"(p));
  return a;
}
__device__ __forceinline__ void cpasync16(uint32_t dst, const void* src) {
  asm volatile("cp.async.cg.shared.global [%0], [%1], 16;" :: "r"(dst), "l"(src));
}
#define CP_COMMIT() asm volatile("cp.async.commit_group;" ::: "memory")
#define CP_WAIT1()  asm volatile("cp.async.wait_group 1;" ::: "memory")
__device__ __forceinline__ void mma16(float* c, const uint32_t* a, const uint32_t* b) {
  asm volatile(
      "mma.sync.aligned.m16n8k16.row.col.f32.f16.f16.f32 "
      "{%0,%1,%2,%3}, {%4,%5,%6,%7}, {%8,%9}, {%0,%1,%2,%3};"
      : "+f"(c[0]), "+f"(c[1]), "+f"(c[2]), "+f"(c[3])
      : "r"(a[0]), "r"(a[1]), "r"(a[2]), "r"(a[3]), "r"(b[0]), "r"(b[1]));
}
__device__ __forceinline__ void ldsm4(uint32_t r[4], uint32_t addr) {
  asm volatile("ldmatrix.sync.aligned.m8n8.x4.shared.b16 {%0,%1,%2,%3}, [%4];"
               : "=r"(r[0]), "=r"(r[1]), "=r"(r[2]), "=r"(r[3]) : "r"(addr));
}

// ---------------- routing ----------------
__global__ void zero_cnt_kernel() {
  if (threadIdx.x < NEXP) g_cnt[threadIdx.x] = 0;
}
__global__ void route_kernel(const int* __restrict__ ids, const float* __restrict__ tw) {
  int t = blockIdx.x * blockDim.x + threadIdx.x;
  if (t >= NT) return;
  int e0 = ids[t * NTOPK + 0] & 3;
  int e1 = ids[t * NTOPK + 1] & 3;
  float w0 = tw[t * NTOPK + 0], w1 = tw[t * NTOPK + 1];
  if (e0 == e1) {
    int p = atomicAdd(&g_cnt[e0], 1);
    g_tok[e0 * NT + p] = t; g_wgt[e0 * NT + p] = w0 + w1;
  } else {
    int p0 = atomicAdd(&g_cnt[e0], 1);
    g_tok[e0 * NT + p0] = t; g_wgt[e0 * NT + p0] = w0;
    int p1 = atomicAdd(&g_cnt[e1], 1);
    g_tok[e1 * NT + p1] = t; g_wgt[e1 * NT + p1] = w1;
  }
}

// ---------------- f32 -> fp16 conversion (once per launch) -----------------
__global__ void cvt_f2h(const float4* __restrict__ src, int which, int n4) {
  int i = blockIdx.x * blockDim.x + threadIdx.x;
  if (i >= n4) return;
  __half* dst = (which == 0) ? g_w13h : (which == 1) ? g_w2h : g_hidh;
  float4 v = src[i];
  __half2 h0 = __floats2half2_rn(v.x, v.y);
  __half2 h1 = __floats2half2_rn(v.z, v.w);
  uint2 u = make_uint2(*(uint32_t*)&h0, *(uint32_t*)&h1);
  *(uint2*)(dst + (size_t)i * 4) = u;
}

// ---------------- fragment compute: warp tile 64(m) x 32(n), BK=64 ----------
// acc[mt 0..3][nt 0..3][4]; per k16 step: A 4 ldsm.x4, B 2 ldsm.x4, 16 MMAs
__device__ __forceinline__ void compute_tile(uint32_t aB, uint32_t bB,
                                             float acc[4][4][4]) {
#pragma unroll
  for (int s = 0; s < 4; ++s) {            // four k16 steps per BK=64
    uint32_t a[4][4], b[2][4];
#pragma unroll
    for (int mt = 0; mt < 4; ++mt) ldsm4(a[mt], aB + mt * 2304 + s * 32);
#pragma unroll
    for (int p = 0; p < 2; ++p)  ldsm4(b[p], bB + p * 2304 + s * 32);
#pragma unroll
    for (int mt = 0; mt < 4; ++mt)
#pragma unroll
      for (int p = 0; p < 2; ++p) {
        mma16(acc[mt][2 * p],     a[mt], &b[p][0]);
        mma16(acc[mt][2 * p + 1], a[mt], &b[p][2]);
      }
  }
}

// ---------------- GEMM1 + fused SiLU*gate -----------------------------------
// tile 128(m) x 128(B-rows: interleaved W1/W3 of 64 I-cols), K=NH, BK=64
__global__ __launch_bounds__(THREADS, 2) void gemm1_tc() {
  const int e   = blockIdx.z;
  const int cnt = g_cnt[e];
  const int m0  = blockIdx.x * 128;
  if (m0 >= cnt) return;
  const int n0 = blockIdx.y * 64;    // I columns

  extern __shared__ char smraw[];
  SMem& sm = *(SMem*)smraw;
  const int tid = threadIdx.x;

  if (tid < 128) {
    int m = m0 + tid;
    sm.toks[tid] = g_tok[e * NT + (m < cnt ? m : cnt - 1)];
  }
  __syncthreads();

  // loaders: 2 threads/row, each 4x16B (64B half-row)
  const int rA = tid >> 1, seg = tid & 1;
  const __half* asrc = g_hidh + (size_t)sm.toks[rA] * NH + seg * 32;
  const __half* bsrc = g_w13h +
      ((size_t)e * 2 * NI + (size_t)(rA & 1) * NI + n0 + (rA >> 1)) * NH + seg * 32;

  const uint32_t smA = smem_u32(&sm.A[0][0]);
  const uint32_t smB = smem_u32(&sm.B[0][0]);
  const uint32_t dA = smA + rA * 144 + seg * 64;
  const uint32_t dB = smB + rA * 144 + seg * 64;

#pragma unroll
  for (int s = 0; s < NSTAGE - 1; ++s) {
#pragma unroll
    for (int g = 0; g < 4; ++g) {
      cpasync16(dA + s * ASTG + g * 16, asrc + s * BK + g * 8);
      cpasync16(dB + s * BSTG + g * 16, bsrc + s * BK + g * 8);
    }
    CP_COMMIT();
  }

  const int lane = tid & 31, warp = tid >> 5;
  const int wM = warp & 1, wN = warp >> 1;
  const int gid = lane >> 2, tg = lane & 3;
  const uint32_t aBase = smA +
      (uint32_t)(((wM * 64 + (lane & 7) + ((lane >> 3) & 1) * 8) * HSTRIDE +
                  (lane >> 4) * 8) * 2);
  const uint32_t bBase = smB +
      (uint32_t)(((wN * 32 + (lane & 7) + (lane >> 4) * 8) * HSTRIDE +
                  ((lane >> 3) & 1) * 8) * 2);

  float acc[4][4][4];
#pragma unroll
  for (int mt = 0; mt < 4; ++mt)
#pragma unroll
    for (int nt = 0; nt < 4; ++nt)
#pragma unroll
      for (int q = 0; q < 4; ++q) acc[mt][nt][q] = 0.0f;

  const int KB = NH / BK;   // 32
  int st = 0, sn = NSTAGE - 1;
  for (int kb = 0; kb < KB; ++kb) {
    CP_WAIT1();
    __syncthreads();
    compute_tile(aBase + st * ASTG, bBase + st * BSTG, acc);
    const int kn = kb + NSTAGE - 1;
    if (kn < KB) {
#pragma unroll
      for (int g = 0; g < 4; ++g) {
        cpasync16(dA + sn * ASTG + g * 16, asrc + kn * BK + g * 8);
        cpasync16(dB + sn * BSTG + g * 16, bsrc + kn * BK + g * 8);
      }
    }
    CP_COMMIT();
    st = (st + 1 == NSTAGE) ? 0 : st + 1;
    sn = (sn + 1 == NSTAGE) ? 0 : sn + 1;
  }

  // epilogue: act = silu(g1)*g3 (c0=g1, c1=g3 via interleaved B rows)
#pragma unroll
  for (int mt = 0; mt < 4; ++mt) {
    const int mrow0 = m0 + wM * 64 + mt * 16 + gid;
    const int mrow1 = mrow0 + 8;
#pragma unroll
    for (int p = 0; p < 2; ++p)
#pragma unroll
      for (int b8 = 0; b8 < 2; ++b8) {
        const int nt = 2 * p + b8;
        const int i = n0 + wN * 16 + p * 8 + b8 * 4 + tg;
        float g1 = acc[mt][nt][0], g3 = acc[mt][nt][1];
        float v0 = g1 / (1.0f + __expf(-g1)) * g3;
        g1 = acc[mt][nt][2]; g3 = acc[mt][nt][3];
        float v1 = g1 / (1.0f + __expf(-g1)) * g3;
        if (mrow0 < cnt) g_act[((size_t)e * NT + mrow0) * NI + i] = __float2half_rn(v0);
        if (mrow1 < cnt) g_act[((size_t)e * NT + mrow1) * NI + i] = __float2half_rn(v1);
      }
  }
}

// ---------------- GEMM2 + weighted scatter -----------------------------------
// tile 128(m) x 128(h), K=NI, BK=64
__global__ __launch_bounds__(THREADS, 2) void gemm2_tc(float* __restrict__ out) {
  const int e   = blockIdx.z;
  const int cnt = g_cnt[e];
  const int m0  = blockIdx.x * 128;
  if (m0 >= cnt) return;
  const int n0 = blockIdx.y * 128;

  extern __shared__ char smraw[];
  SMem& sm = *(SMem*)smraw;
  const int tid = threadIdx.x;

  if (tid < 128) {
    int m = m0 + tid;
    int mc = m < cnt ? m : cnt - 1;
    sm.toks[tid] = g_tok[e * NT + mc];
    sm.wgts[tid] = g_wgt[e * NT + mc];
  }
  __syncthreads();

  const int rA = tid >> 1, seg = tid & 1;
  const int mA = (m0 + rA) < cnt ? (m0 + rA) : cnt - 1;
  const __half* asrc = g_act + ((size_t)e * NT + mA) * NI + seg * 32;
  const __half* bsrc = g_w2h + ((size_t)e * NH + n0 + rA) * NI + seg * 32;

  const uint32_t smA = smem_u32(&sm.A[0][0]);
  const uint32_t smB = smem_u32(&sm.B[0][0]);
  const uint32_t dA = smA + rA * 144 + seg * 64;
  const uint32_t dB = smB + rA * 144 + seg * 64;

#pragma unroll
  for (int s = 0; s < NSTAGE - 1; ++s) {
#pragma unroll
    for (int g = 0; g < 4; ++g) {
      cpasync16(dA + s * ASTG + g * 16, asrc + s * BK + g * 8);
      cpasync16(dB + s * BSTG + g * 16, bsrc + s * BK + g * 8);
    }
    CP_COMMIT();
  }

  const int lane = tid & 31, warp = tid >> 5;
  const int wM = warp & 1, wN = warp >> 1;
  const int gid = lane >> 2, tg = lane & 3;
  const uint32_t aBase = smA +
      (uint32_t)(((wM * 64 + (lane & 7) + ((lane >> 3) & 1) * 8) * HSTRIDE +
                  (lane >> 4) * 8) * 2);
  const uint32_t bBase = smB +
      (uint32_t)(((wN * 32 + (lane & 7) + (lane >> 4) * 8) * HSTRIDE +
                  ((lane >> 3) & 1) * 8) * 2);

  float acc[4][4][4];
#pragma unroll
  for (int mt = 0; mt < 4; ++mt)
#pragma unroll
    for (int nt = 0; nt < 4; ++nt)
#pragma unroll
      for (int q = 0; q < 4; ++q) acc[mt][nt][q] = 0.0f;

  const int KB = NI / BK;   // 88
  int st = 0, sn = NSTAGE - 1;
  for (int kb = 0; kb < KB; ++kb) {
    CP_WAIT1();
    __syncthreads();
    compute_tile(aBase + st * ASTG, bBase + st * BSTG, acc);
    const int kn = kb + NSTAGE - 1;
    if (kn < KB) {
#pragma unroll
      for (int g = 0; g < 4; ++g) {
        cpasync16(dA + sn * ASTG + g * 16, asrc + kn * BK + g * 8);
        cpasync16(dB + sn * BSTG + g * 16, bsrc + kn * BK + g * 8);
      }
    }
    CP_COMMIT();
    st = (st + 1 == NSTAGE) ? 0 : st + 1;
    sn = (sn + 1 == NSTAGE) ? 0 : sn + 1;
  }

  // epilogue: out[tok, h] += wgt * acc
#pragma unroll
  for (int mt = 0; mt < 4; ++mt) {
    const int lr0 = wM * 64 + mt * 16 + gid;
    const int lr1 = lr0 + 8;
    const bool v0 = (m0 + lr0) < cnt;
    const bool v1 = (m0 + lr1) < cnt;
    const int   t0 = sm.toks[lr0], t1 = sm.toks[lr1];
    const float w0 = sm.wgts[lr0], w1 = sm.wgts[lr1];
#pragma unroll
    for (int p = 0; p < 2; ++p)
#pragma unroll
      for (int b8 = 0; b8 < 2; ++b8) {
        const int nt = 2 * p + b8;
        const int h = n0 + wN * 32 + p * 16 + b8 * 8 + 2 * tg;
        if (v0) {
          atomicAdd(&out[(size_t)t0 * NH + h],     w0 * acc[mt][nt][0]);
          atomicAdd(&out[(size_t)t0 * NH + h + 1], w0 * acc[mt][nt][1]);
        }
        if (v1) {
          atomicAdd(&out[(size_t)t1 * NH + h],     w1 * acc[mt][nt][2]);
          atomicAdd(&out[(size_t)t1 * NH + h + 1], w1 * acc[mt][nt][3]);
        }
      }
  }
}

// ---------------- launcher ----------------
extern "C" void kernel_launch(void* const* d_in, const int* in_sizes, int n_in,
                              void* d_out, int out_size) {
  const float* hidden = (const float*)d_in[0];
  const float* w13    = (const float*)d_in[1];
  const float* w2     = (const float*)d_in[2];
  const float* tw     = (const float*)d_in[3];
  const int*   ids    = (const int*)d_in[4];
  float*       out    = (float*)d_out;
  (void)in_sizes; (void)n_in;

  cudaFuncSetAttribute(gemm1_tc, cudaFuncAttributeMaxDynamicSharedMemorySize, SMEM_BYTES);
  cudaFuncSetAttribute(gemm2_tc, cudaFuncAttributeMaxDynamicSharedMemorySize, SMEM_BYTES);

  cudaMemsetAsync(out, 0, (size_t)out_size * sizeof(float), 0);
  zero_cnt_kernel<<<1, 32>>>();
  route_kernel<<<(NT + 255) / 256, 256>>>(ids, tw);

  // f32 -> fp16 conversions (active experts only: first 4 of 8)
  const int n4_w13 = NEXP * 2 * NI * NH / 4;
  const int n4_w2  = NEXP * NH * NI / 4;
  const int n4_hid = NT * NH / 4;
  cvt_f2h<<<(n4_w13 + 255) / 256, 256>>>((const float4*)w13, 0, n4_w13);
  cvt_f2h<<<(n4_w2  + 255) / 256, 256>>>((const float4*)w2,  1, n4_w2);
  cvt_f2h<<<(n4_hid + 255) / 256, 256>>>((const float4*)hidden, 2, n4_hid);

  gemm1_tc<<<dim3(NT / 128, NI / 64, NEXP), THREADS, SMEM_BYTES>>>();
  gemm2_tc<<<dim3(NT / 128, NH / 128, NEXP), THREADS, SMEM_BYTES>>>(out);
}